// round 7
// baseline (speedup 1.0000x reference)
#include <cuda_runtime.h>
#include <math.h>
#include <stdint.h>

// Problem constants (fixed by setup_inputs)
#define NN      262144
#define HH      192
#define SS      16384
#define IND     16
#define MAXDEG  32
#define KA      224          // extended K: [feat 16 | u 192 | pad 16]

// ---------------- device scratch (no allocation allowed) -------------------
__device__ uint16_t g_ah[(size_t)NN * KA];   // A operand hi (feat|u|0)
__device__ uint16_t g_al[(size_t)NN * KA];   // A operand lo
__device__ float    g_y[(size_t)NN * HH];    // x @ W1_top
__device__ float    g_z[(size_t)SS * HH];    // x_sup @ W1_bot + b1
__device__ uint16_t g_ph[(size_t)SS * HH];   // pooled GELU hi
__device__ uint16_t g_pl[(size_t)SS * HH];   // pooled GELU lo
__device__ float    g_v[2 * IND * HH];       // V = W_in @ W1_{top,bot} (fp32)
// weight operands [n][k] split bf16
__device__ uint16_t g_b1a_h[HH * KA], g_b1a_l[HH * KA];   // [V1a | W1a | 0]
__device__ uint16_t g_b1b_h[HH * KA], g_b1b_l[HH * KA];   // [V1b | W1b | 0]
__device__ uint16_t g_b2_h[HH * HH],  g_b2_l[HH * HH];

// ---------------- helpers ---------------------------------------------------
__device__ __forceinline__ uint16_t f2bf(float x) {
    uint16_t r;
    asm("cvt.rn.bf16.f32 %0, %1;" : "=h"(r) : "f"(x));
    return r;
}
__device__ __forceinline__ void split_bf16(float x, uint16_t& h, uint16_t& l) {
    h = f2bf(x);
    float hf = __uint_as_float(((uint32_t)h) << 16);
    l = f2bf(x - hf);
}

__device__ __forceinline__ void cp16(uint32_t s, const void* g) {
    asm volatile("cp.async.cg.shared.global [%0], [%1], 16;" :: "r"(s), "l"(g));
}
__device__ __forceinline__ void cp_commit() {
    asm volatile("cp.async.commit_group;" ::: "memory");
}
template<int N>
__device__ __forceinline__ void cp_wait() {
    asm volatile("cp.async.wait_group %0;" :: "n"(N) : "memory");
}

__device__ __forceinline__ void ldm_x4(uint32_t addr, uint32_t r[4]) {
    asm volatile("ldmatrix.sync.aligned.m8n8.x4.shared.b16 {%0,%1,%2,%3}, [%4];"
                 : "=r"(r[0]), "=r"(r[1]), "=r"(r[2]), "=r"(r[3]) : "r"(addr));
}

__device__ __forceinline__ void mma_bf16(float c[4], const uint32_t a[4],
                                         uint32_t b0, uint32_t b1) {
    asm volatile(
        "mma.sync.aligned.m16n8k16.row.col.f32.bf16.bf16.f32 "
        "{%0,%1,%2,%3}, {%4,%5,%6,%7}, {%8,%9}, {%0,%1,%2,%3};"
        : "+f"(c[0]), "+f"(c[1]), "+f"(c[2]), "+f"(c[3])
        : "r"(a[0]), "r"(a[1]), "r"(a[2]), "r"(a[3]), "r"(b0), "r"(b1));
}

__device__ __forceinline__ float gelu_exact(float v) {
    return 0.5f * v * (1.0f + erff(v * 0.70710678118654752f));
}

// ---------------- GEMM shared-memory layout ---------------------------------
// Per stage: A hi 128x32 (80B rows) | A lo | B hi 192x32 | B lo
#define BUF_AH  0
#define BUF_AL  10240
#define BUF_BH  20480
#define BUF_BL  35840
#define BUF_SZ  51200
#define NBUF    3
#define OFF_IDX (NBUF * BUF_SZ)       // 153600
#define SMEM_SZ (OFF_IDX + 512)       // 154112

// ---------------------------------------------------------------------------
// GEMM: C[M,192] = A[M,KCH*32] @ B (+bias). Split-bf16 3-term, full-N tile.
// 512 threads / 16 warps (4M x 4N), warp tile 32x48, 3-stage cp.async.
// ---------------------------------------------------------------------------
template<int KCH, bool GATHER>
__global__ void __launch_bounds__(512, 1) gemm_kernel(
    const uint16_t* __restrict__ Ah, const uint16_t* __restrict__ Al,
    const uint16_t* __restrict__ Bh, const uint16_t* __restrict__ Bl,
    const int* __restrict__ ridx, const float* __restrict__ bias,
    float* __restrict__ C)
{
    constexpr int AS = KCH * 32;      // A & B k-stride
    extern __shared__ char sm[];
    uint32_t sbase = (uint32_t)__cvta_generic_to_shared(sm);
    int tid = threadIdx.x;
    int lane = tid & 31;
    int wid = tid >> 5;
    int m0 = blockIdx.x * 128;
    int* IDX = (int*)(sm + OFF_IDX);

    if (GATHER) {
        if (tid < 128) IDX[tid] = ridx[m0 + tid];
        __syncthreads();
    }

    // staging lambda
    auto stage = [&](int kc, int buf) {
        int k0 = kc * 32;
        uint32_t sb = sbase + buf * BUF_SZ;
        {   // A: 128 rows x 4 chunks of 16B, exactly 512 ids
            int row = tid >> 2, j = tid & 3;
            int ar = GATHER ? IDX[row] : (m0 + row);
            size_t go = (size_t)ar * AS + k0 + j * 8;
            uint32_t sa = sb + BUF_AH + row * 80 + j * 16;
            cp16(sa, Ah + go);
            cp16(sa + (BUF_AL - BUF_AH), Al + go);
        }
#pragma unroll
        for (int i = 0; i < 2; i++) {   // B: 192 rows x 4 chunks = 768 ids
            int id = tid + 512 * i;
            if (id < 768) {
                int row = id >> 2, j = id & 3;
                size_t go = (size_t)row * AS + k0 + j * 8;
                uint32_t sa = sb + BUF_BH + row * 80 + j * 16;
                cp16(sa, Bh + go);
                cp16(sa + (BUF_BL - BUF_BH), Bl + go);
            }
        }
    };

    float c[2][6][4];
#pragma unroll
    for (int mt = 0; mt < 2; mt++)
#pragma unroll
        for (int nt = 0; nt < 6; nt++)
#pragma unroll
            for (int k = 0; k < 4; k++) c[mt][nt][k] = 0.0f;

    int wm = wid >> 2;              // 0..3 (M quadrant of 32 rows)
    int wn = (wid & 3) * 48;        // N offset
    uint32_t a_lrow = (lane & 7) + ((lane >> 3) & 1) * 8;
    uint32_t a_lcol = (lane >> 4) * 16;
    uint32_t b_lrow = (lane & 7) + (lane >> 4) * 8;
    uint32_t b_lcol = ((lane >> 3) & 1) * 16;

    stage(0, 0); cp_commit();
    stage(1, 1); cp_commit();

    for (int kc = 0; kc < KCH; kc++) {
        if (kc < KCH - 1) cp_wait<1>(); else cp_wait<0>();
        __syncthreads();
        if (kc < KCH - 2) {
            stage(kc + 2, (kc + 2) % NBUF);
            cp_commit();
        }

        uint32_t sb = sbase + (kc % NBUF) * BUF_SZ;
#pragma unroll
        for (int ks = 0; ks < 2; ks++) {
            uint32_t ah[2][4], al[2][4];
#pragma unroll
            for (int mt = 0; mt < 2; mt++) {
                uint32_t ro = (wm * 32 + mt * 16 + a_lrow) * 80 + ks * 32 + a_lcol;
                ldm_x4(sb + BUF_AH + ro, ah[mt]);
                ldm_x4(sb + BUF_AL + ro, al[mt]);
            }
#pragma unroll
            for (int np = 0; np < 3; np++) {
                uint32_t bo = (wn + np * 16 + b_lrow) * 80 + ks * 32 + b_lcol;
                uint32_t bh[4], bl[4];
                ldm_x4(sb + BUF_BH + bo, bh);
                ldm_x4(sb + BUF_BL + bo, bl);
#pragma unroll
                for (int mt = 0; mt < 2; mt++) {
                    mma_bf16(c[mt][2 * np],     ah[mt], bh[0], bh[1]);
                    mma_bf16(c[mt][2 * np],     al[mt], bh[0], bh[1]);
                    mma_bf16(c[mt][2 * np],     ah[mt], bl[0], bl[1]);
                    mma_bf16(c[mt][2 * np + 1], ah[mt], bh[2], bh[3]);
                    mma_bf16(c[mt][2 * np + 1], al[mt], bh[2], bh[3]);
                    mma_bf16(c[mt][2 * np + 1], ah[mt], bl[2], bl[3]);
                }
            }
        }
    }

    // epilogue
    int r = lane >> 2, q = lane & 3;
#pragma unroll
    for (int mt = 0; mt < 2; mt++) {
        int row = m0 + wm * 32 + mt * 16 + r;
#pragma unroll
        for (int nt = 0; nt < 6; nt++) {
            int col = wn + nt * 8 + 2 * q;
            float b0 = bias ? bias[col] : 0.0f;
            float b1 = bias ? bias[col + 1] : 0.0f;
            *(float2*)(C + (size_t)row * HH + col) =
                make_float2(c[mt][nt][0] + b0, c[mt][nt][1] + b1);
            *(float2*)(C + (size_t)(row + 8) * HH + col) =
                make_float2(c[mt][nt][2] + b0, c[mt][nt][3] + b1);
        }
    }
}

// ---------------------------------------------------------------------------
// Embed: A row = [split(feat) | split(b_in + sincos(pos)) | 0]. No FMAs.
// 224 threads = 2 node-groups x 112 col-pairs; 16 nodes/block.
// ---------------------------------------------------------------------------
__global__ void embed_kernel(const float* __restrict__ feat,
                             const float* __restrict__ pos,
                             const float* __restrict__ b_in) {
    int n0 = blockIdx.x * 16;
    int tid = threadIdx.x;
    __shared__ float f[16][IND];
    __shared__ float p[16][3];
    for (int id = tid; id < 16 * IND; id += 224)
        f[id >> 4][id & 15] = feat[(n0 + (id >> 4)) * IND + (id & 15)];
    if (tid < 48) p[tid / 3][tid % 3] = pos[(n0 + tid / 3) * 3 + tid % 3];

    int sub = tid / 112;          // node parity
    int cp = tid % 112;
    int c = 2 * cp;               // column pair (c, c+1), 0..222
    bool isfeat = (c < 16);
    bool ispad = (c >= 208);

    int d = 0;
    float om0 = 0.f, om1 = 0.f, b0 = 0.f, b1 = 0.f;
    bool issin = true;
    if (!isfeat && !ispad) {
        int cu = c - 16;
        d = cu >> 6;
        int t = cu & 63;
        int j = t & 31;
        om0 = exp2f(-(float)j * (13.2877123795494f / 32.0f));
        om1 = exp2f(-(float)(j + 1) * (13.2877123795494f / 32.0f));
        issin = (t < 32);
        b0 = b_in[cu];
        b1 = b_in[cu + 1];
    }
    __syncthreads();

    for (int nn = sub; nn < 16; nn += 2) {
        float v0, v1;
        if (isfeat) {
            v0 = f[nn][c];
            v1 = f[nn][c + 1];
        } else if (ispad) {
            v0 = 0.f; v1 = 0.f;
        } else {
            float pd = p[nn][d];
            float a0 = pd * om0, a1 = pd * om1;
            v0 = b0 + (issin ? __sinf(a0) : __cosf(a0));
            v1 = b1 + (issin ? __sinf(a1) : __cosf(a1));
        }
        uint16_t h0, l0, h1, l1;
        split_bf16(v0, h0, l0);
        split_bf16(v1, h1, l1);
        size_t o = (size_t)(n0 + nn) * KA + c;
        *(uint32_t*)(g_ah + o) = (uint32_t)h0 | ((uint32_t)h1 << 16);
        *(uint32_t*)(g_al + o) = (uint32_t)l0 | ((uint32_t)l1 << 16);
    }
}

// ---------------------------------------------------------------------------
// V = W_in @ W1_{top,bot}: grid 32 (s*16+i), block 192 (n)
// ---------------------------------------------------------------------------
__global__ void vprep_kernel(const float* __restrict__ W_in,
                             const float* __restrict__ W1) {
    int s = blockIdx.x >> 4, i = blockIdx.x & 15, n = threadIdx.x;
    float acc = 0.0f;
    for (int cc = 0; cc < HH; cc++)
        acc = fmaf(W_in[i * HH + cc], W1[(size_t)(cc + s * HH) * HH + n], acc);
    g_v[(s * IND + i) * HH + n] = acc;
}

// ---------------------------------------------------------------------------
// Build B operands [V | W1 | 0] transposed/split. grid 192 (n), block 224 (k)
// ---------------------------------------------------------------------------
__global__ void bprep_kernel(const float* __restrict__ W1) {
    int n = blockIdx.x, k = threadIdx.x;
#pragma unroll
    for (int s = 0; s < 2; s++) {
        float v;
        if (k < IND) v = g_v[(s * IND + k) * HH + n];
        else if (k < IND + HH) v = W1[(size_t)(k - IND + s * HH) * HH + n];
        else v = 0.0f;
        uint16_t h, l;
        split_bf16(v, h, l);
        if (s == 0) { g_b1a_h[n * KA + k] = h; g_b1a_l[n * KA + k] = l; }
        else        { g_b1b_h[n * KA + k] = h; g_b1b_l[n * KA + k] = l; }
    }
}

__global__ void b2prep_kernel(const float* __restrict__ W2) {
    int n = blockIdx.x, k = threadIdx.x;
    uint16_t h, l;
    split_bf16(W2[(size_t)k * HH + n], h, l);
    g_b2_h[n * HH + k] = h;
    g_b2_l[n * HH + k] = l;
}

// ---------------------------------------------------------------------------
// Pool: pool[s,c] = mean_e GELU(y[src_e,c] + z[s,c]); split bf16 output.
// 192 threads = 4 supernodes x 48 threads; float4 channels per thread.
// ---------------------------------------------------------------------------
__global__ void pool_kernel(const int* __restrict__ src_idx) {
    int tid = threadIdx.x;
    int sgrp = tid / 48;
    int t = tid % 48;
    int s = blockIdx.x * 4 + sgrp;
    int c = t * 4;

    __shared__ int srcs[4][MAXDEG];
    if (tid < 128) srcs[tid >> 5][tid & 31] = src_idx[blockIdx.x * 128 + tid];
    __syncthreads();

    float4 z = *(const float4*)(g_z + (size_t)s * HH + c);
    float4 acc = make_float4(0.f, 0.f, 0.f, 0.f);
#pragma unroll 4
    for (int e = 0; e < MAXDEG; e++) {
        const float4 v = *(const float4*)(g_y + (size_t)srcs[sgrp][e] * HH + c);
        acc.x += gelu_exact(v.x + z.x);
        acc.y += gelu_exact(v.y + z.y);
        acc.z += gelu_exact(v.z + z.z);
        acc.w += gelu_exact(v.w + z.w);
    }
    const float inv = 1.0f / 32.0f;
    uint16_t h[4], l[4];
    split_bf16(acc.x * inv, h[0], l[0]);
    split_bf16(acc.y * inv, h[1], l[1]);
    split_bf16(acc.z * inv, h[2], l[2]);
    split_bf16(acc.w * inv, h[3], l[3]);
    size_t o = (size_t)s * HH + c;
    *(uint2*)(g_ph + o) = make_uint2((uint32_t)h[0] | ((uint32_t)h[1] << 16),
                                     (uint32_t)h[2] | ((uint32_t)h[3] << 16));
    *(uint2*)(g_pl + o) = make_uint2((uint32_t)l[0] | ((uint32_t)l[1] << 16),
                                     (uint32_t)l[2] | ((uint32_t)l[3] << 16));
}

// ---------------------------------------------------------------------------
// launch
// ---------------------------------------------------------------------------
extern "C" void kernel_launch(void* const* d_in, const int* in_sizes, int n_in,
                              void* d_out, int out_size) {
    const float* feat  = (const float*)d_in[0];
    const float* pos   = (const float*)d_in[1];
    const int*   sup   = (const int*)  d_in[2];
    const int*   src   = (const int*)  d_in[4];
    const float* W_in  = (const float*)d_in[6];
    const float* b_in  = (const float*)d_in[7];
    const float* W1    = (const float*)d_in[8];
    const float* b1    = (const float*)d_in[9];
    const float* W2    = (const float*)d_in[10];
    const float* b2    = (const float*)d_in[11];
    float* out = (float*)d_out;

    uint16_t *pah, *pal, *pph, *ppl;
    uint16_t *pb1ah, *pb1al, *pb1bh, *pb1bl, *pb2h, *pb2l;
    float *py, *pz;
    cudaGetSymbolAddress((void**)&pah,   g_ah);
    cudaGetSymbolAddress((void**)&pal,   g_al);
    cudaGetSymbolAddress((void**)&py,    g_y);
    cudaGetSymbolAddress((void**)&pz,    g_z);
    cudaGetSymbolAddress((void**)&pph,   g_ph);
    cudaGetSymbolAddress((void**)&ppl,   g_pl);
    cudaGetSymbolAddress((void**)&pb1ah, g_b1a_h);
    cudaGetSymbolAddress((void**)&pb1al, g_b1a_l);
    cudaGetSymbolAddress((void**)&pb1bh, g_b1b_h);
    cudaGetSymbolAddress((void**)&pb1bl, g_b1b_l);
    cudaGetSymbolAddress((void**)&pb2h,  g_b2_h);
    cudaGetSymbolAddress((void**)&pb2l,  g_b2_l);

    cudaFuncSetAttribute(gemm_kernel<7, true>,
                         cudaFuncAttributeMaxDynamicSharedMemorySize, SMEM_SZ);
    cudaFuncSetAttribute(gemm_kernel<7, false>,
                         cudaFuncAttributeMaxDynamicSharedMemorySize, SMEM_SZ);
    cudaFuncSetAttribute(gemm_kernel<6, false>,
                         cudaFuncAttributeMaxDynamicSharedMemorySize, SMEM_SZ);

    // prep + embed
    vprep_kernel<<<32, HH>>>(W_in, W1);
    bprep_kernel<<<HH, KA>>>(W1);
    b2prep_kernel<<<HH, HH>>>(W2);
    embed_kernel<<<NN / 16, 224>>>(feat, pos, b_in);

    // z = A[sup] @ B1b + b1
    gemm_kernel<7, true><<<SS / 128, 512, SMEM_SZ>>>(
        pah, pal, pb1bh, pb1bl, sup, b1, pz);

    // y = A @ B1a (big GEMM)
    gemm_kernel<7, false><<<NN / 128, 512, SMEM_SZ>>>(
        pah, pal, pb1ah, pb1al, nullptr, nullptr, py);

    // pool[s] = mean_e GELU(y[src_e] + z[s])
    pool_kernel<<<SS / 4, HH>>>(src);

    // out = pool @ W2 + b2
    gemm_kernel<6, false><<<SS / 128, 512, SMEM_SZ>>>(
        pph, ppl, pb2h, pb2l, nullptr, b2, out);
}

// round 8
// speedup vs baseline: 1.0537x; 1.0537x over previous
#include <cuda_runtime.h>
#include <math.h>
#include <stdint.h>

// Problem constants (fixed by setup_inputs)
#define NN      262144
#define HH      192
#define SS      16384
#define EE      524288
#define IND     16
#define MAXDEG  32

// ---------------- device scratch (no allocation allowed) -------------------
__device__ uint16_t g_xh[(size_t)NN * HH];   // bf16 hi of x
__device__ uint16_t g_xl[(size_t)NN * HH];   // bf16 lo of x
__device__ float    g_y[(size_t)NN * HH];    // x @ W1_top (fp32)
__device__ float    g_z[(size_t)SS * HH];    // x_sup @ W1_bot + b1
__device__ uint16_t g_ph[(size_t)SS * HH];   // pooled GELU, bf16 hi
__device__ uint16_t g_pl[(size_t)SS * HH];   // pooled GELU, bf16 lo
// transposed split weights [n][k], bf16
__device__ uint16_t g_w1a_h[HH * HH], g_w1a_l[HH * HH];
__device__ uint16_t g_w1b_h[HH * HH], g_w1b_l[HH * HH];
__device__ uint16_t g_w2_h[HH * HH],  g_w2_l[HH * HH];

// ---------------- helpers ---------------------------------------------------
__device__ __forceinline__ uint16_t f2bf(float x) {
    uint16_t r;
    asm("cvt.rn.bf16.f32 %0, %1;" : "=h"(r) : "f"(x));
    return r;
}
__device__ __forceinline__ void split_bf16(float x, uint16_t& h, uint16_t& l) {
    h = f2bf(x);
    float hf = __uint_as_float(((uint32_t)h) << 16);
    l = f2bf(x - hf);
}

__device__ __forceinline__ void cp16(uint32_t s, const void* g) {
    asm volatile("cp.async.cg.shared.global [%0], [%1], 16;"
                 :: "r"(s), "l"(g));
}
__device__ __forceinline__ void cp_commit() {
    asm volatile("cp.async.commit_group;" ::: "memory");
}
template<int N>
__device__ __forceinline__ void cp_wait() {
    asm volatile("cp.async.wait_group %0;" :: "n"(N) : "memory");
}

__device__ __forceinline__ void ldm_x4(uint32_t addr, uint32_t r[4]) {
    asm volatile("ldmatrix.sync.aligned.m8n8.x4.shared.b16 {%0,%1,%2,%3}, [%4];"
                 : "=r"(r[0]), "=r"(r[1]), "=r"(r[2]), "=r"(r[3]) : "r"(addr));
}

__device__ __forceinline__ void mma_bf16(float c[4], const uint32_t a[4],
                                         uint32_t b0, uint32_t b1) {
    asm volatile(
        "mma.sync.aligned.m16n8k16.row.col.f32.bf16.bf16.f32 "
        "{%0,%1,%2,%3}, {%4,%5,%6,%7}, {%8,%9}, {%0,%1,%2,%3};"
        : "+f"(c[0]), "+f"(c[1]), "+f"(c[2]), "+f"(c[3])
        : "r"(a[0]), "r"(a[1]), "r"(a[2]), "r"(a[3]), "r"(b0), "r"(b1));
}

__device__ __forceinline__ float gelu_exact(float v) {
    return 0.5f * v * (1.0f + erff(v * 0.70710678118654752f));
}

// ---------------- GEMM shared-memory layout ---------------------------------
// Per buffer: A hi 128x32 bf16 (80B rows) | A lo | B hi 96x32 | B lo
#define BUF_AH  0
#define BUF_AL  10240
#define BUF_BH  20480
#define BUF_BL  28160
#define BUF_SZ  35840
#define NBUF    3
#define OFF_IDX (NBUF * BUF_SZ)       // 107520
#define SMEM_SZ (OFF_IDX + 512)       // 108032

template<bool GATHER>
__device__ __forceinline__ void stage_tiles(
    int kc, int buf, int tid, int m0, int n0,
    const uint16_t* __restrict__ Ah, const uint16_t* __restrict__ Al,
    const uint16_t* __restrict__ Bh, const uint16_t* __restrict__ Bl,
    const int* __restrict__ IDX, uint32_t sbase)
{
    int k0 = kc * 32;
    uint32_t sb = sbase + buf * BUF_SZ;
    // A: 128 rows x 32 k, 4 x 16B chunks per row (hi & lo)
#pragma unroll
    for (int i = 0; i < 2; i++) {
        int id = tid + 256 * i;
        int row = id >> 2, j = id & 3;
        int ar = GATHER ? IDX[row] : (m0 + row);
        size_t go = (size_t)ar * HH + k0 + j * 8;
        uint32_t sa = sb + BUF_AH + row * 80 + j * 16;
        cp16(sa, Ah + go);
        cp16(sa + (BUF_AL - BUF_AH), Al + go);
    }
    // B: 96 rows x 32 k
#pragma unroll
    for (int i = 0; i < 2; i++) {
        int id = tid + 256 * i;
        if (id < 384) {
            int row = id >> 2, j = id & 3;
            size_t go = (size_t)(n0 + row) * HH + k0 + j * 8;
            uint32_t sa = sb + BUF_BH + row * 80 + j * 16;
            cp16(sa, Bh + go);
            cp16(sa + (BUF_BL - BUF_BH), Bl + go);
        }
    }
}

// ---------------------------------------------------------------------------
// GEMM: C[M,192] = A @ W (+bias), split-bf16 3-term, 3-stage cp.async pipeline.
// CTA tile 128(M) x 96(N); grid.x = Mtiles*2 (N halves). Optional row gather.
// ---------------------------------------------------------------------------
template<bool GATHER>
__global__ void __launch_bounds__(256, 2) gemm_kernel(
    const uint16_t* __restrict__ Ah, const uint16_t* __restrict__ Al,
    const uint16_t* __restrict__ Bh, const uint16_t* __restrict__ Bl,
    const int* __restrict__ ridx, const float* __restrict__ bias,
    float* __restrict__ C)
{
    extern __shared__ char sm[];
    uint32_t sbase = (uint32_t)__cvta_generic_to_shared(sm);
    int tid = threadIdx.x;
    int lane = tid & 31;
    int wid = tid >> 5;
    int mtile = blockIdx.x >> 1;
    int n0 = (blockIdx.x & 1) * 96;
    int m0 = mtile * 128;
    int* IDX = (int*)(sm + OFF_IDX);

    if (GATHER) {
        if (tid < 128) IDX[tid] = ridx[m0 + tid];
        __syncthreads();
    }

    float c[2][6][4];
#pragma unroll
    for (int mt = 0; mt < 2; mt++)
#pragma unroll
        for (int nt = 0; nt < 6; nt++)
#pragma unroll
            for (int k = 0; k < 4; k++) c[mt][nt][k] = 0.0f;

    int wm = wid >> 1;              // 0..3 (M quadrant of 32)
    int wn = (wid & 1) * 48;        // N half within 96
    uint32_t a_lrow = (lane & 7) + ((lane >> 3) & 1) * 8;
    uint32_t a_lcol = (lane >> 4) * 16;
    uint32_t b_lrow = (lane & 7) + (lane >> 4) * 8;
    uint32_t b_lcol = ((lane >> 3) & 1) * 16;

    stage_tiles<GATHER>(0, 0, tid, m0, n0, Ah, Al, Bh, Bl, IDX, sbase);
    cp_commit();
    stage_tiles<GATHER>(1, 1, tid, m0, n0, Ah, Al, Bh, Bl, IDX, sbase);
    cp_commit();

    for (int kc = 0; kc < 6; kc++) {
        if (kc < 5) cp_wait<1>(); else cp_wait<0>();
        __syncthreads();
        if (kc < 4) {
            stage_tiles<GATHER>(kc + 2, (kc + 2) % NBUF, tid, m0, n0,
                                Ah, Al, Bh, Bl, IDX, sbase);
            cp_commit();
        }

        uint32_t sb = sbase + (kc % NBUF) * BUF_SZ;
#pragma unroll
        for (int ks = 0; ks < 2; ks++) {
            uint32_t ah[2][4], al[2][4];
#pragma unroll
            for (int mt = 0; mt < 2; mt++) {
                uint32_t ro = (wm * 32 + mt * 16 + a_lrow) * 80 + ks * 32 + a_lcol;
                ldm_x4(sb + BUF_AH + ro, ah[mt]);
                ldm_x4(sb + BUF_AL + ro, al[mt]);
            }
#pragma unroll
            for (int np = 0; np < 3; np++) {
                uint32_t bo = (wn + np * 16 + b_lrow) * 80 + ks * 32 + b_lcol;
                uint32_t bh[4], bl[4];
                ldm_x4(sb + BUF_BH + bo, bh);
                ldm_x4(sb + BUF_BL + bo, bl);
#pragma unroll
                for (int mt = 0; mt < 2; mt++) {
                    mma_bf16(c[mt][2 * np],     ah[mt], bh[0], bh[1]);
                    mma_bf16(c[mt][2 * np],     al[mt], bh[0], bh[1]);
                    mma_bf16(c[mt][2 * np],     ah[mt], bl[0], bl[1]);
                    mma_bf16(c[mt][2 * np + 1], ah[mt], bh[2], bh[3]);
                    mma_bf16(c[mt][2 * np + 1], al[mt], bh[2], bh[3]);
                    mma_bf16(c[mt][2 * np + 1], ah[mt], bl[2], bl[3]);
                }
            }
        }
    }

    // epilogue
    int r = lane >> 2, q = lane & 3;
#pragma unroll
    for (int mt = 0; mt < 2; mt++) {
        int row = m0 + wm * 32 + mt * 16 + r;
#pragma unroll
        for (int nt = 0; nt < 6; nt++) {
            int col = n0 + wn + nt * 8 + 2 * q;
            float b0 = bias ? bias[col] : 0.0f;
            float b1 = bias ? bias[col + 1] : 0.0f;
            *(float2*)(C + (size_t)row * HH + col) =
                make_float2(c[mt][nt][0] + b0, c[mt][nt][1] + b1);
            *(float2*)(C + (size_t)(row + 8) * HH + col) =
                make_float2(c[mt][nt][2] + b0, c[mt][nt][3] + b1);
        }
    }
}

// ---------------------------------------------------------------------------
// K1: x = feat @ W_in + b_in + sincos(pos); split bf16, packed stores.
// 192 threads; thread owns channel pair (2q, 2q+1); 16 nodes/block, 2 nodes
// per iteration per thread subgroup, float4 feature reads.
// ---------------------------------------------------------------------------
__global__ void node_embed_kernel(const float* __restrict__ feat,
                                  const float* __restrict__ pos,
                                  const float* __restrict__ W_in,
                                  const float* __restrict__ b_in) {
    int n0 = blockIdx.x * 16;
    int tid = threadIdx.x;
    int half = tid / 96;          // node parity for this thread
    int q = tid % 96;
    int c = 2 * q;

    __shared__ __align__(16) float f[16][IND];
    __shared__ float p[16][3];
    if (tid < 128) {
        f[tid >> 4][tid & 15] = feat[(n0 + (tid >> 4)) * IND + (tid & 15)];
        int id2 = tid + 128;
        f[id2 >> 4][id2 & 15] = feat[(n0 + (id2 >> 4)) * IND + (id2 & 15)];
    }
    if (tid < 48) p[tid / 3][tid % 3] = pos[(n0 + tid / 3) * 3 + tid % 3];

    float w0[IND], w1[IND];
#pragma unroll
    for (int i = 0; i < IND; i++) {
        w0[i] = W_in[i * HH + c];
        w1[i] = W_in[i * HH + c + 1];
    }
    float b0 = b_in[c], b1 = b_in[c + 1];

    int d = c >> 6;
    int t = c & 63;               // even -> pair never straddles sin/cos
    int j = t & 31;
    float om0 = exp2f(-(float)j * (13.2877123795494f / 32.0f));
    float om1 = exp2f(-(float)(j + 1) * (13.2877123795494f / 32.0f));
    bool issin = (t < 32);
    __syncthreads();

    // 8 nodes per thread (nn = half, half+2, ...), unrolled by 2 for ILP
#pragma unroll
    for (int it = 0; it < 4; it++) {
        int na = half + 4 * it;
        int nb = na + 2;

        float pa = p[na][d], pb = p[nb][d];
        float a0 = pa * om0, a1 = pa * om1;
        float e0 = issin ? __sinf(a0) : __cosf(a0);
        float e1 = issin ? __sinf(a1) : __cosf(a1);
        float c0 = pb * om0, c1 = pb * om1;
        float e2 = issin ? __sinf(c0) : __cosf(c0);
        float e3 = issin ? __sinf(c1) : __cosf(c1);

        float acc0 = b0 + e0, acc1 = b1 + e1;
        float acc2 = b0 + e2, acc3 = b1 + e3;
#pragma unroll
        for (int i4 = 0; i4 < 4; i4++) {
            float4 va = *(const float4*)&f[na][4 * i4];
            float4 vb = *(const float4*)&f[nb][4 * i4];
            acc0 = fmaf(va.x, w0[4 * i4 + 0], acc0);
            acc1 = fmaf(va.x, w1[4 * i4 + 0], acc1);
            acc2 = fmaf(vb.x, w0[4 * i4 + 0], acc2);
            acc3 = fmaf(vb.x, w1[4 * i4 + 0], acc3);
            acc0 = fmaf(va.y, w0[4 * i4 + 1], acc0);
            acc1 = fmaf(va.y, w1[4 * i4 + 1], acc1);
            acc2 = fmaf(vb.y, w0[4 * i4 + 1], acc2);
            acc3 = fmaf(vb.y, w1[4 * i4 + 1], acc3);
            acc0 = fmaf(va.z, w0[4 * i4 + 2], acc0);
            acc1 = fmaf(va.z, w1[4 * i4 + 2], acc1);
            acc2 = fmaf(vb.z, w0[4 * i4 + 2], acc2);
            acc3 = fmaf(vb.z, w1[4 * i4 + 2], acc3);
            acc0 = fmaf(va.w, w0[4 * i4 + 3], acc0);
            acc1 = fmaf(va.w, w1[4 * i4 + 3], acc1);
            acc2 = fmaf(vb.w, w0[4 * i4 + 3], acc2);
            acc3 = fmaf(vb.w, w1[4 * i4 + 3], acc3);
        }
        uint16_t h0, l0, h1, l1, h2, l2, h3, l3;
        split_bf16(acc0, h0, l0);
        split_bf16(acc1, h1, l1);
        split_bf16(acc2, h2, l2);
        split_bf16(acc3, h3, l3);
        size_t oa = (size_t)(n0 + na) * HH + c;
        size_t ob = (size_t)(n0 + nb) * HH + c;
        *(uint32_t*)(g_xh + oa) = (uint32_t)h0 | ((uint32_t)h1 << 16);
        *(uint32_t*)(g_xl + oa) = (uint32_t)l0 | ((uint32_t)l1 << 16);
        *(uint32_t*)(g_xh + ob) = (uint32_t)h2 | ((uint32_t)h3 << 16);
        *(uint32_t*)(g_xl + ob) = (uint32_t)l2 | ((uint32_t)l3 << 16);
    }
}

// ---------------------------------------------------------------------------
// Weight prep: transposed split [n][k]
// ---------------------------------------------------------------------------
__global__ void wprep_kernel(const float* __restrict__ W,
                             uint16_t* __restrict__ oh,
                             uint16_t* __restrict__ ol) {
    int n = blockIdx.x, k = threadIdx.x;
    uint16_t h, l;
    split_bf16(W[k * HH + n], h, l);
    oh[n * HH + k] = h;
    ol[n * HH + k] = l;
}

// ---------------------------------------------------------------------------
// Pool: pool[s,c] = mean_e GELU(y[src_e,c] + z[s,c]); split bf16 output.
// 192 threads = 4 supernodes x 48 threads; float4 channels per thread.
// ---------------------------------------------------------------------------
__global__ void pool_kernel(const int* __restrict__ src_idx) {
    int tid = threadIdx.x;
    int sgrp = tid / 48;          // 0..3
    int t = tid % 48;
    int s = blockIdx.x * 4 + sgrp;
    int c = t * 4;

    __shared__ int srcs[4][MAXDEG];
    if (tid < 128) srcs[tid >> 5][tid & 31] = src_idx[blockIdx.x * 128 + tid];
    __syncthreads();

    float4 z = *(const float4*)(g_z + (size_t)s * HH + c);
    float4 acc = make_float4(0.f, 0.f, 0.f, 0.f);
#pragma unroll 4
    for (int e = 0; e < MAXDEG; e++) {
        const float4 v = *(const float4*)(g_y + (size_t)srcs[sgrp][e] * HH + c);
        acc.x += gelu_exact(v.x + z.x);
        acc.y += gelu_exact(v.y + z.y);
        acc.z += gelu_exact(v.z + z.z);
        acc.w += gelu_exact(v.w + z.w);
    }
    const float inv = 1.0f / 32.0f;
    uint16_t h[4], l[4];
    split_bf16(acc.x * inv, h[0], l[0]);
    split_bf16(acc.y * inv, h[1], l[1]);
    split_bf16(acc.z * inv, h[2], l[2]);
    split_bf16(acc.w * inv, h[3], l[3]);
    size_t o = (size_t)s * HH + c;
    *(uint2*)(g_ph + o) = make_uint2((uint32_t)h[0] | ((uint32_t)h[1] << 16),
                                     (uint32_t)h[2] | ((uint32_t)h[3] << 16));
    *(uint2*)(g_pl + o) = make_uint2((uint32_t)l[0] | ((uint32_t)l[1] << 16),
                                     (uint32_t)l[2] | ((uint32_t)l[3] << 16));
}

// ---------------------------------------------------------------------------
// launch
// ---------------------------------------------------------------------------
extern "C" void kernel_launch(void* const* d_in, const int* in_sizes, int n_in,
                              void* d_out, int out_size) {
    const float* feat  = (const float*)d_in[0];
    const float* pos   = (const float*)d_in[1];
    const int*   sup   = (const int*)  d_in[2];
    const int*   src   = (const int*)  d_in[4];
    const float* W_in  = (const float*)d_in[6];
    const float* b_in  = (const float*)d_in[7];
    const float* W1    = (const float*)d_in[8];
    const float* b1    = (const float*)d_in[9];
    const float* W2    = (const float*)d_in[10];
    const float* b2    = (const float*)d_in[11];
    float* out = (float*)d_out;

    uint16_t *pxh, *pxl, *pph, *ppl;
    uint16_t *pw1ah, *pw1al, *pw1bh, *pw1bl, *pw2h, *pw2l;
    float *py, *pz;
    cudaGetSymbolAddress((void**)&pxh,   g_xh);
    cudaGetSymbolAddress((void**)&pxl,   g_xl);
    cudaGetSymbolAddress((void**)&py,    g_y);
    cudaGetSymbolAddress((void**)&pz,    g_z);
    cudaGetSymbolAddress((void**)&pph,   g_ph);
    cudaGetSymbolAddress((void**)&ppl,   g_pl);
    cudaGetSymbolAddress((void**)&pw1ah, g_w1a_h);
    cudaGetSymbolAddress((void**)&pw1al, g_w1a_l);
    cudaGetSymbolAddress((void**)&pw1bh, g_w1b_h);
    cudaGetSymbolAddress((void**)&pw1bl, g_w1b_l);
    cudaGetSymbolAddress((void**)&pw2h,  g_w2_h);
    cudaGetSymbolAddress((void**)&pw2l,  g_w2_l);

    cudaFuncSetAttribute(gemm_kernel<true>,
                         cudaFuncAttributeMaxDynamicSharedMemorySize, SMEM_SZ);
    cudaFuncSetAttribute(gemm_kernel<false>,
                         cudaFuncAttributeMaxDynamicSharedMemorySize, SMEM_SZ);

    // weight prep + node embed
    wprep_kernel<<<HH, HH>>>(W1, pw1ah, pw1al);
    wprep_kernel<<<HH, HH>>>(W1 + (size_t)HH * HH, pw1bh, pw1bl);
    wprep_kernel<<<HH, HH>>>(W2, pw2h, pw2l);
    node_embed_kernel<<<NN / 16, HH>>>(feat, pos, W_in, b_in);

    // z = x[sup] @ W1_bot + b1
    gemm_kernel<true><<<(SS / 128) * 2, 256, SMEM_SZ>>>(
        pxh, pxl, pw1bh, pw1bl, sup, b1, pz);

    // y = x @ W1_top (big GEMM)
    gemm_kernel<false><<<(NN / 128) * 2, 256, SMEM_SZ>>>(
        pxh, pxl, pw1ah, pw1al, nullptr, nullptr, py);

    // pool[s] = mean_e GELU(y[src_e] + z[s])
    pool_kernel<<<SS / 4, HH>>>(src);

    // out = pool @ W2 + b2
    gemm_kernel<false><<<(SS / 128) * 2, 256, SMEM_SZ>>>(
        pph, ppl, pw2h, pw2l, nullptr, b2, out);
}